// round 7
// baseline (speedup 1.0000x reference)
#include <cuda_runtime.h>
#include <math.h>

#define N_NODES 4096
#define KDIM    512
#define D_H     64
#define HEADS   8
#define MAXD    192
#define CH      64
#define KSPLIT  8
#define KS      64                  // K per split
#define BM      32
#define ROWBLKS (N_NODES / BM)      // 128
#define GEMM_BLOCKS (ROWBLKS * KSPLIT)  // 1024
#define CSR_BLOCKS  1024

typedef unsigned long long ull;

// ---------------- packed f32x2 helpers (Blackwell) ----------------
__device__ __forceinline__ ull pack2(float a) {
    ull r;
    asm("mov.b64 %0, {%1, %1};" : "=l"(r) : "f"(a));
    return r;
}
__device__ __forceinline__ void fma2(ull& d, ull a, ull b) {
    asm("fma.rn.f32x2 %0, %1, %2, %0;" : "+l"(d) : "l"(a), "l"(b));
}
__device__ __forceinline__ void add2(ull& d, ull a) {
    asm("add.rn.f32x2 %0, %0, %1;" : "+l"(d) : "l"(a));
}
__device__ __forceinline__ void unpack2(ull v, float& lo, float& hi) {
    asm("mov.b64 {%0, %1}, %2;" : "=f"(lo), "=f"(hi) : "l"(v));
}

// ---------------- scratch ----------------
__device__ float g_x [N_NODES * D_H];
__device__ float g_el[N_NODES * HEADS];
__device__ float g_er[N_NODES * HEADS];
__device__ float g_h1[N_NODES * D_H * HEADS];
__device__ float g_h2[N_NODES * D_H * HEADS];
__device__ float g_part[KSPLIT * N_NODES * D_H];
__device__ int   g_cols[N_NODES * MAXD];
__device__ int   g_deg [N_NODES];

// ---- split-K GEMM (+ fused CSR build in extra blocks) --------------------
__global__ __launch_bounds__(128) void gemm_csr_kernel(const float* __restrict__ adj,
                                                       const float* __restrict__ A,
                                                       const float* __restrict__ B) {
    if (blockIdx.x >= GEMM_BLOCKS) {
        // ---------------- CSR build ----------------
        int warp = (blockIdx.x - GEMM_BLOCKS) * 4 + (threadIdx.x >> 5);
        int lane = threadIdx.x & 31;
        const float4* a = reinterpret_cast<const float4*>(adj + (size_t)warp * N_NODES);
        int* outc = g_cols + warp * MAXD;
        int base = 0;
        for (int j0 = 0; j0 < N_NODES; j0 += 128) {
            float4 v = a[(j0 >> 2) + lane];
            float vv[4] = {v.x, v.y, v.z, v.w};
            #pragma unroll
            for (int c = 0; c < 4; c++) {
                unsigned m = __ballot_sync(0xffffffffu, vv[c] != 0.0f);
                if (vv[c] != 0.0f) {
                    int pos = base + __popc(m & ((1u << lane) - 1u));
                    if (pos < MAXD) outc[pos] = j0 + lane * 4 + c;
                }
                base += __popc(m);
            }
        }
        if (lane == 0) g_deg[warp] = base < MAXD ? base : MAXD;
        return;
    }

    // ------- GEMM partial: 32 rows x 64 cols, K slice 64, 4x4 micro-tile ---
    __shared__ float AsT[32][36];   // [k][row], row XOR-swizzled in groups of 4
    __shared__ float Bs[32][64];
    int tid = threadIdx.x;
    int tx = tid & 15, ty = tid >> 4;
    int rowBase = (blockIdx.x >> 3) * BM;
    int k0      = (blockIdx.x & 7) * KS;

    float4 a_n[2], b_n[4];
    #pragma unroll
    for (int s = 0; s < 2; s++) {
        int idx = tid + 128 * s;
        a_n[s] = *reinterpret_cast<const float4*>(
            A + (size_t)(rowBase + (idx >> 3)) * KDIM + k0 + ((idx & 7) << 2));
    }
    #pragma unroll
    for (int s = 0; s < 4; s++) {
        int idx = tid + 128 * s;
        b_n[s] = *reinterpret_cast<const float4*>(
            B + (size_t)(k0 + (idx >> 4)) * 64 + ((idx & 15) << 2));
    }

    ull acc[4][2] = {{0,0},{0,0},{0,0},{0,0}};

    for (int kt = 0; kt < KS; kt += 32) {
        #pragma unroll
        for (int s = 0; s < 2; s++) {
            int idx = tid + 128 * s;
            int row = idx >> 3;
            int kk  = (idx & 7) << 2;
            float av[4] = {a_n[s].x, a_n[s].y, a_n[s].z, a_n[s].w};
            #pragma unroll
            for (int i = 0; i < 4; i++) {
                int k = kk + i;
                AsT[k][row ^ ((( k >> 3) & 3) << 2)] = av[i];
            }
        }
        #pragma unroll
        for (int s = 0; s < 4; s++) {
            int idx = tid + 128 * s;
            *reinterpret_cast<float4*>(&Bs[idx >> 4][(idx & 15) << 2]) = b_n[s];
        }
        __syncthreads();
        if (kt + 32 < KS) {
            #pragma unroll
            for (int s = 0; s < 2; s++) {
                int idx = tid + 128 * s;
                a_n[s] = *reinterpret_cast<const float4*>(
                    A + (size_t)(rowBase + (idx >> 3)) * KDIM + k0 + kt + 32 + ((idx & 7) << 2));
            }
            #pragma unroll
            for (int s = 0; s < 4; s++) {
                int idx = tid + 128 * s;
                b_n[s] = *reinterpret_cast<const float4*>(
                    B + (size_t)(k0 + kt + 32 + (idx >> 4)) * 64 + ((idx & 15) << 2));
            }
        }
        #pragma unroll
        for (int k = 0; k < 32; k++) {
            int sr = (ty ^ ((k >> 3) & 3)) << 2;
            float4 av = *reinterpret_cast<const float4*>(&AsT[k][sr]);
            ulonglong2 bb = *reinterpret_cast<const ulonglong2*>(&Bs[k][tx * 4]);
            ull pa0 = pack2(av.x), pa1 = pack2(av.y), pa2 = pack2(av.z), pa3 = pack2(av.w);
            fma2(acc[0][0], pa0, bb.x); fma2(acc[0][1], pa0, bb.y);
            fma2(acc[1][0], pa1, bb.x); fma2(acc[1][1], pa1, bb.y);
            fma2(acc[2][0], pa2, bb.x); fma2(acc[2][1], pa2, bb.y);
            fma2(acc[3][0], pa3, bb.x); fma2(acc[3][1], pa3, bb.y);
        }
        __syncthreads();
    }

    float* P = g_part + (size_t)(blockIdx.x & 7) * (N_NODES * D_H);
    #pragma unroll
    for (int i = 0; i < 4; i++) {
        int r = rowBase + ty * 4 + i;
        ulonglong2 v; v.x = acc[i][0]; v.y = acc[i][1];
        *reinterpret_cast<ulonglong2*>(P + (size_t)r * 64 + tx * 4) = v;
    }
}

// ---- reduce 8 split-K partials (fixed order) + el/er projection ----------
__global__ __launch_bounds__(256) void reduce_proj_kernel(const float* __restrict__ al,
                                                          const float* __restrict__ ar,
                                                          float* __restrict__ X, int H) {
    __shared__ float sC[4][64];
    __shared__ float sAl[512];
    __shared__ float sAr[512];
    int tid = threadIdx.x;
    int r = tid >> 6, d = tid & 63;
    int row = blockIdx.x * 4 + r;
    size_t off = (size_t)row * 64 + d;
    const size_t SZ = (size_t)N_NODES * D_H;
    float p0 = g_part[off]          + g_part[SZ + off];
    float p1 = g_part[2*SZ + off]   + g_part[3*SZ + off];
    float p2 = g_part[4*SZ + off]   + g_part[5*SZ + off];
    float p3 = g_part[6*SZ + off]   + g_part[7*SZ + off];
    float v = (p0 + p1) + (p2 + p3);
    X[off] = v;
    sC[r][d] = v;
    for (int idx = tid; idx < 64 * H; idx += 256) {
        sAl[idx] = al[idx];
        sAr[idx] = ar[idx];
    }
    __syncthreads();
    if (tid < 4 * H) {
        int rr = (H == 8) ? (tid >> 3) : tid;
        int h  = (H == 8) ? (tid & 7)  : 0;
        float sl = 0.f, sr = 0.f;
        #pragma unroll
        for (int dd = 0; dd < 64; dd++) {
            float cv = sC[rr][dd];
            sl += cv * sAl[dd * H + h];
            sr += cv * sAr[dd * H + h];
        }
        g_el[(blockIdx.x * 4 + rr) * H + h] = sl;
        g_er[(blockIdx.x * 4 + rr) * H + h] = sr;
    }
}

// ---------------- 8-head aggregation: block per node, 128 threads ----------
// thread = (h, q). 6 instr/neighbor: LDS col + LDS.64 w + LDG.128 + 2 fma2 + add2.
__global__ __launch_bounds__(128) void agg8_kernel(const float* __restrict__ bias,
                                                   float* __restrict__ out, int act) {
    int i   = blockIdx.x;
    int tid = threadIdx.x;
    int h   = tid >> 4;
    int q   = tid & 15;

    __shared__ int   s_cols[CH];
    __shared__ float s_el[HEADS];
    __shared__ ull   s_w[HEADS][CH];   // transposed: contiguous in jj

    if (tid < HEADS) s_el[tid] = g_el[i * HEADS + tid];
    int deg = g_deg[i];
    const int* cols = g_cols + (size_t)i * MAXD;
    const float* xq = g_x + q * 4;

    ull acc0 = 0ull, acc1 = 0ull, sw2 = 0ull;

    for (int j0 = 0; j0 < deg; j0 += CH) {
        int cl = min(CH, deg - j0);
        if (tid < cl) s_cols[tid] = cols[j0 + tid];
        __syncthreads();
        for (int idx = tid; idx < cl * HEADS; idx += 128) {
            int jj = idx >> 3, hh = idx & 7;
            float s = s_el[hh] + g_er[s_cols[jj] * HEADS + hh];
            s = (s >= 0.f) ? s : 0.2f * s;
            s_w[hh][jj] = pack2(__expf(s));
        }
        __syncthreads();
        #pragma unroll 8
        for (int jj = 0; jj < cl; jj++) {
            ull pw = s_w[h][jj];
            ulonglong2 xv = *reinterpret_cast<const ulonglong2*>(xq + (size_t)s_cols[jj] * D_H);
            fma2(acc0, pw, xv.x);
            fma2(acc1, pw, xv.y);
            add2(sw2, pw);
        }
        __syncthreads();
    }

    float sw, dmy;
    unpack2(sw2, sw, dmy);
    float inv = 1.0f / fmaxf(sw, 1e-12f);
    float4 bv = *reinterpret_cast<const float4*>(bias + q * 4);
    float v0, v1, v2, v3;
    unpack2(acc0, v0, v1);
    unpack2(acc1, v2, v3);
    v0 = v0 * inv + bv.x; v1 = v1 * inv + bv.y;
    v2 = v2 * inv + bv.z; v3 = v3 * inv + bv.w;
    if (act) {
        v0 = (v0 > 0.f) ? v0 : expm1f(v0);
        v1 = (v1 > 0.f) ? v1 : expm1f(v1);
        v2 = (v2 > 0.f) ? v2 : expm1f(v2);
        v3 = (v3 > 0.f) ? v3 : expm1f(v3);
    }
    float4 ov = make_float4(v0, v1, v2, v3);
    *reinterpret_cast<float4*>(out + (size_t)i * (HEADS * D_H) + h * D_H + q * 4) = ov;
}

// ---------------- 1-head aggregation: block per node, 64 threads -----------
__global__ __launch_bounds__(64) void agg1_kernel(const float* __restrict__ bias,
                                                  float* __restrict__ out) {
    int i   = blockIdx.x;
    int tid = threadIdx.x;   // = d

    __shared__ int   s_cols[CH];
    __shared__ float s_w[CH];

    float eli = g_el[i];
    int deg = g_deg[i];
    const int* cols = g_cols + (size_t)i * MAXD;
    float acc = 0.f, sw = 0.f;

    for (int j0 = 0; j0 < deg; j0 += CH) {
        int cl = min(CH, deg - j0);
        if (tid < cl) {
            int c = cols[j0 + tid];
            s_cols[tid] = c;
            float s = eli + g_er[c];
            s = (s >= 0.f) ? s : 0.2f * s;
            s_w[tid] = __expf(s);
        }
        __syncthreads();
        #pragma unroll 8
        for (int jj = 0; jj < cl; jj++) {
            float wv = s_w[jj];
            acc += wv * g_x[(size_t)s_cols[jj] * D_H + tid];
            sw  += wv;
        }
        __syncthreads();
    }

    float v = acc / fmaxf(sw, 1e-12f) + bias[tid];
    out[(size_t)i * D_H + tid] = v;
}

// ---------------- launch ---------------------------------------------------
extern "C" void kernel_launch(void* const* d_in, const int* in_sizes, int n_in,
                              void* d_out, int out_size) {
    const float* adj  = (const float*)d_in[0];
    const float* feat = (const float*)d_in[1];
    const float* W0   = (const float*)d_in[2];
    const float* al0  = (const float*)d_in[3];
    const float* ar0  = (const float*)d_in[4];
    const float* b0   = (const float*)d_in[5];
    const float* W1   = (const float*)d_in[6];
    const float* al1  = (const float*)d_in[7];
    const float* ar1  = (const float*)d_in[8];
    const float* b1   = (const float*)d_in[9];
    const float* W2   = (const float*)d_in[10];
    const float* al2  = (const float*)d_in[11];
    const float* ar2  = (const float*)d_in[12];
    const float* b2   = (const float*)d_in[13];
    float* out = (float*)d_out;

    float *x, *h1, *h2;
    cudaGetSymbolAddress((void**)&x,  g_x);
    cudaGetSymbolAddress((void**)&h1, g_h1);
    cudaGetSymbolAddress((void**)&h2, g_h2);

    // layer 0 (CSR build fused into the GEMM launch as extra blocks)
    gemm_csr_kernel<<<GEMM_BLOCKS + CSR_BLOCKS, 128>>>(adj, feat, W0);
    reduce_proj_kernel<<<N_NODES / 4, 256>>>(al0, ar0, x, HEADS);
    agg8_kernel<<<N_NODES, 128>>>(b0, h1, 1);

    // layer 1
    gemm_csr_kernel<<<GEMM_BLOCKS, 128>>>(adj, h1, W1);
    reduce_proj_kernel<<<N_NODES / 4, 256>>>(al1, ar1, x, HEADS);
    agg8_kernel<<<N_NODES, 128>>>(b1, h2, 1);

    // layer 2
    gemm_csr_kernel<<<GEMM_BLOCKS, 128>>>(adj, h2, W2);
    reduce_proj_kernel<<<N_NODES / 4, 256>>>(al2, ar2, x, 1);
    agg1_kernel<<<N_NODES, 64>>>(b2, out);
}